// round 5
// baseline (speedup 1.0000x reference)
#include <cuda_runtime.h>
#include <cuda_bf16.h>
#include <math.h>
#include <stdint.h>

// Problem dims
#define BB   64
#define SS   512
#define DD   768
#define WW   256
#define HH   384
#define FOURH 1536
#define CC   425
#define K2H  768
#define MM   (BB*SS)      // 32768 rows

// Recurrence config
#define NCD   64          // CTAs per direction (128 total <= 148 SMs)
#define CH    6           // h-indices per CTA (64*6 = 384)
#define RR    24          // gate rows per CTA (4 gates * CH)
#define RTH   128

// -------- scratch (device globals; no allocation allowed) --------
__device__ __nv_bfloat16 g_xhi[MM * DD];
__device__ __nv_bfloat16 g_xlo[MM * DD];
__device__ float g_xpf[MM * FOURH];
__device__ float g_xpb[MM * FOURH];
__device__ __nv_bfloat16 g_f1hi[MM * K2H];
__device__ __nv_bfloat16 g_f1lo[MM * K2H];
__device__ float g_hbuf[2][HH * BB];
__device__ unsigned g_bar[2][SS];
__device__ __nv_bfloat16 g_wihf_hi[FOURH * DD], g_wihf_lo[FOURH * DD];
__device__ __nv_bfloat16 g_wihb_hi[FOURH * DD], g_wihb_lo[FOURH * DD];
__device__ __nv_bfloat16 g_wlin_hi[CC * K2H],  g_wlin_lo[CC * K2H];

// ---------------- small helpers ----------------
__device__ __forceinline__ uint32_t smem_u32(const void* p) {
    uint32_t a;
    asm("{ .reg .u64 t; cvta.to.shared.u64 t, %1; cvt.u32.u64 %0, t; }"
        : "=r"(a) : "l"(p));
    return a;
}
__device__ __forceinline__ void cp16(uint32_t d, const void* s, bool v) {
    int sz = v ? 16 : 0;
    asm volatile("cp.async.cg.shared.global [%0], [%1], 16, %2;\n"
                 :: "r"(d), "l"(s), "r"(sz));
}
#define CP_COMMIT() asm volatile("cp.async.commit_group;\n")
#define CP_WAIT(n)  asm volatile("cp.async.wait_group %0;\n" :: "n"(n))

#define LDM4(r, addr) \
    asm volatile("ldmatrix.sync.aligned.m8n8.x4.shared.b16 {%0,%1,%2,%3}, [%4];" \
        : "=r"((r)[0]), "=r"((r)[1]), "=r"((r)[2]), "=r"((r)[3]) : "r"(addr))

#define MMA(d, a, b0, b1) \
    asm volatile("mma.sync.aligned.m16n8k16.row.col.f32.bf16.bf16.f32 " \
        "{%0,%1,%2,%3},{%4,%5,%6,%7},{%8,%9},{%0,%1,%2,%3};" \
        : "+f"((d)[0]), "+f"((d)[1]), "+f"((d)[2]), "+f"((d)[3]) \
        : "r"((a)[0]), "r"((a)[1]), "r"((a)[2]), "r"((a)[3]), "r"(b0), "r"(b1))

// fast, accurate-enough activations (clamped; rel err ~1e-6)
__device__ __forceinline__ float sigf(float x) {
    x = fminf(fmaxf(x, -30.0f), 30.0f);
    return __fdividef(1.0f, 1.0f + __expf(-x));
}
__device__ __forceinline__ float tanhfast(float x) {
    x = fminf(fmaxf(x, -15.0f), 15.0f);
    float e = __expf(2.0f * x);
    return __fdividef(e - 1.0f, e + 1.0f);
}

// ---------------- init: zero state + barriers (every replay) ----------------
__global__ void init_kernel()
{
    int tid = threadIdx.x + blockIdx.x * blockDim.x;
    int nt  = blockDim.x * gridDim.x;
    float* hb = &g_hbuf[0][0];
    for (int i = tid; i < 2 * HH * BB; i += nt) hb[i] = 0.0f;
    unsigned* bp = &g_bar[0][0];
    for (int i = tid; i < 2 * SS; i += nt) bp[i] = 0u;
}

// ---------------- fp32 -> (hi, lo) bf16 split ----------------
__global__ void cvt_kernel(const float* __restrict__ in,
                           __nv_bfloat16* __restrict__ hi,
                           __nv_bfloat16* __restrict__ lo, int n)
{
    int i = blockIdx.x * blockDim.x + threadIdx.x;
    if (i < n) {
        float v = in[i];
        __nv_bfloat16 h = __float2bfloat16(v);
        hi[i] = h;
        lo[i] = __float2bfloat16(v - __bfloat162float(h));
    }
}

// ---------------- segment mean pool (writes split bf16) ----------------
__global__ void pool_kernel(const float* __restrict__ f0,
                            const int*   __restrict__ counts,
                            __nv_bfloat16* __restrict__ xhi,
                            __nv_bfloat16* __restrict__ xlo)
{
    __shared__ int s_start[WW];
    __shared__ int s_cnt[WW];
    int b = blockIdx.x;
    int tid = threadIdx.x;
    if (tid == 0) {
        int run = 0;
        for (int j = 0; j < WW; ++j) {
            int c = counts[b * WW + j];
            s_start[j] = run; s_cnt[j] = c; run += c;
        }
    }
    __syncthreads();
    const float* fb = f0 + (size_t)b * SS * DD;
    __nv_bfloat16* xh = xhi + (size_t)b * SS * DD;
    __nv_bfloat16* xl = xlo + (size_t)b * SS * DD;
    for (int idx = tid; idx < WW * DD; idx += blockDim.x) {
        int j = idx / DD, d = idx - j * DD;
        int st = s_start[j], c = s_cnt[j];
        float v = 0.0f;
        for (int p = 0; p < c; ++p) v += fb[(size_t)(st + p) * DD + d];
        v /= (float)c;
        __nv_bfloat16 h = __float2bfloat16(v);
        xh[idx] = h;
        xl[idx] = __float2bfloat16(v - __bfloat162float(h));
    }
    for (int idx = tid; idx < (SS - WW) * DD; idx += blockDim.x) {
        float v = fb[WW * DD + idx];
        __nv_bfloat16 h = __float2bfloat16(v);
        xh[WW * DD + idx] = h;
        xl[WW * DD + idx] = __float2bfloat16(v - __bfloat162float(h));
    }
}

// ---------------- split-bf16 tensor-core GEMM (mma.sync) ----------------
// C[M,N] = (Ahi+Alo)[M,K] * (Bhi+Blo)[N,K]^T + bias1 + bias2
// 3-term split: Ah*Bh + Ah*Bl + Al*Bh (fp32 accumulate).
// 128x128 tile, BK=32, 256 threads (8 warps, 2x4 grid of 64x32 warp tiles).
// MMAs issued term-by-term: 16 independent MMAs between reuses of any acc
// register (kills the RAW chain that throttled the round-3 version).
#define ARRB  (128 * 80)
#define STGB  (4 * ARRB)

__global__ void __launch_bounds__(256, 1)
gemm3_kernel(const __nv_bfloat16* __restrict__ Ahi, const __nv_bfloat16* __restrict__ Alo,
             const __nv_bfloat16* __restrict__ Bhi, const __nv_bfloat16* __restrict__ Blo,
             const float* __restrict__ bias1, const float* __restrict__ bias2,
             float* __restrict__ C, int N, int K)
{
    extern __shared__ char smem[];
    uint32_t sb = smem_u32(smem);
    int tid = threadIdx.x, lane = tid & 31, wid = tid >> 5;
    int wm = wid >> 2, wn = wid & 3;
    int bm = blockIdx.y, bn = blockIdx.x;

    int lr = tid >> 1;
    int lc = (tid & 1) * 2;
    int arow = bm * 128 + lr;
    int brow = bn * 128 + lr;
    bool bv  = brow < N;
    const __nv_bfloat16* pAh = Ahi + (size_t)arow * K;
    const __nv_bfloat16* pAl = Alo + (size_t)arow * K;
    const __nv_bfloat16* pBh = Bhi + (size_t)(bv ? brow : 0) * K;
    const __nv_bfloat16* pBl = Blo + (size_t)(bv ? brow : 0) * K;
    uint32_t sd = sb + lr * 80 + lc * 16;

    float acc[4][4][4];
#pragma unroll
    for (int a = 0; a < 4; ++a)
#pragma unroll
        for (int b = 0; b < 4; ++b)
#pragma unroll
            for (int c = 0; c < 4; ++c) acc[a][b][c] = 0.0f;

    int KT = K >> 5;

    {
        uint32_t d = sd;
#pragma unroll
        for (int cc = 0; cc < 2; ++cc) {
            cp16(d + cc * 16 + 0 * ARRB, pAh + (lc + cc) * 8, true);
            cp16(d + cc * 16 + 1 * ARRB, pAl + (lc + cc) * 8, true);
            cp16(d + cc * 16 + 2 * ARRB, pBh + (lc + cc) * 8, bv);
            cp16(d + cc * 16 + 3 * ARRB, pBl + (lc + cc) * 8, bv);
        }
        CP_COMMIT();
    }

    int la  = lane & 15, lc4 = lane >> 4;
    int lb  = (lane & 7) + ((lane & 16) >> 1);
    int lbc = (lane >> 3) & 1;

    for (int i = 0; i < KT; ++i) {
        CP_WAIT(0);
        __syncthreads();
        if (i + 1 < KT) {
            int ko = (i + 1) << 5;
            uint32_t d = sd + ((i + 1) & 1) * STGB;
#pragma unroll
            for (int cc = 0; cc < 2; ++cc) {
                cp16(d + cc * 16 + 0 * ARRB, pAh + ko + (lc + cc) * 8, true);
                cp16(d + cc * 16 + 1 * ARRB, pAl + ko + (lc + cc) * 8, true);
                cp16(d + cc * 16 + 2 * ARRB, pBh + ko + (lc + cc) * 8, bv);
                cp16(d + cc * 16 + 3 * ARRB, pBl + ko + (lc + cc) * 8, bv);
            }
            CP_COMMIT();
        }
        uint32_t st = sb + (i & 1) * STGB;
#pragma unroll
        for (int kh = 0; kh < 2; ++kh) {
            uint32_t aaddr = st + (wm * 64 + la) * 80 + (kh * 2 + lc4) * 16;
            uint32_t ah[4][4], al[4][4];
#pragma unroll
            for (int mt = 0; mt < 4; ++mt) {
                LDM4(ah[mt], aaddr + mt * 1280);
                LDM4(al[mt], aaddr + mt * 1280 + ARRB);
            }
            uint32_t bbase = st + 2 * ARRB + (wn * 32 + lb) * 80 + (kh * 2 + lbc) * 16;
            uint32_t bh[2][4], bl[2][4];
#pragma unroll
            for (int ntp = 0; ntp < 2; ++ntp) {
                LDM4(bh[ntp], bbase + ntp * 1280);
                LDM4(bl[ntp], bbase + ntp * 1280 + ARRB);
            }
            // term 1: Ah*Bh — 16 independent MMAs
#pragma unroll
            for (int mt = 0; mt < 4; ++mt)
#pragma unroll
                for (int ntp = 0; ntp < 2; ++ntp) {
                    MMA(acc[mt][2 * ntp + 0], ah[mt], bh[ntp][0], bh[ntp][1]);
                    MMA(acc[mt][2 * ntp + 1], ah[mt], bh[ntp][2], bh[ntp][3]);
                }
            // term 2: Ah*Bl
#pragma unroll
            for (int mt = 0; mt < 4; ++mt)
#pragma unroll
                for (int ntp = 0; ntp < 2; ++ntp) {
                    MMA(acc[mt][2 * ntp + 0], ah[mt], bl[ntp][0], bl[ntp][1]);
                    MMA(acc[mt][2 * ntp + 1], ah[mt], bl[ntp][2], bl[ntp][3]);
                }
            // term 3: Al*Bh
#pragma unroll
            for (int mt = 0; mt < 4; ++mt)
#pragma unroll
                for (int ntp = 0; ntp < 2; ++ntp) {
                    MMA(acc[mt][2 * ntp + 0], al[mt], bh[ntp][0], bh[ntp][1]);
                    MMA(acc[mt][2 * ntp + 1], al[mt], bh[ntp][2], bh[ntp][3]);
                }
        }
        __syncthreads();
    }

    // epilogue
#pragma unroll
    for (int mt = 0; mt < 4; ++mt) {
        int m0 = bm * 128 + wm * 64 + mt * 16 + (lane >> 2);
#pragma unroll
        for (int nt = 0; nt < 4; ++nt) {
            int n0 = bn * 128 + wn * 32 + nt * 8 + (lane & 3) * 2;
            float* a = acc[mt][nt];
            if (n0 < N) {
                float bs = bias1[n0] + (bias2 ? bias2[n0] : 0.0f);
                C[(size_t)m0 * N + n0]       = a[0] + bs;
                C[(size_t)(m0 + 8) * N + n0] = a[2] + bs;
            }
            if (n0 + 1 < N) {
                float bs = bias1[n0 + 1] + (bias2 ? bias2[n0 + 1] : 0.0f);
                C[(size_t)m0 * N + n0 + 1]       = a[1] + bs;
                C[(size_t)(m0 + 8) * N + n0 + 1] = a[3] + bs;
            }
        }
    }
}

// ---------------- persistent bidirectional LSTM recurrence ----------------
// 128 CTAs: [0,64) fwd, [64,128) bwd. CH=6 h-indices (24 gate rows) per CTA.
__global__ void __launch_bounds__(RTH, 1)
lstm_kernel(const float* __restrict__ Whh_f, const float* __restrict__ Whh_b)
{
    extern __shared__ float sm[];
    float* h_s     = sm;                         // [384*64]
    float* W_s     = h_s + HH * BB;              // [384*24]  layout [k][r]
    float* gates_s = W_s + HH * RR;              // [24*64]   layout [r][b]
    float* c_s     = gates_s + RR * BB;          // [6*64]
    uint32_t h_s32 = smem_u32(h_s);

    int cta = blockIdx.x;
    int dir = (cta >= NCD) ? 1 : 0;
    int ci  = cta - dir * NCD;
    const float* Whh = dir ? Whh_b : Whh_f;
    const float* xp  = dir ? g_xpb : g_xpf;
    int n0  = ci * CH;
    int tid = threadIdx.x;

    for (int idx = tid; idx < RR * HH; idx += RTH) {
        int r = idx / HH, k = idx - r * HH;
        int gi = r / CH, j = r - gi * CH;
        W_s[k * RR + r] = Whh[(size_t)(gi * HH + n0 + j) * HH + k];
    }
    for (int idx = tid; idx < CH * BB; idx += RTH) c_s[idx] = 0.0f;
    __syncthreads();

    int tb = tid & 15, tr = tid >> 4;     // 16 batch groups x 8 row groups
    int b0 = tb * 4, r0 = tr * 3;
    int gi = r0 / CH;
    int jb = r0 - gi * CH;
    float* hb = &g_hbuf[dir][0];
    const char* hbc = (const char*)hb;

    for (int s = 0; s < SS; ++s) {
        int t = dir ? (SS - 1 - s) : s;

#pragma unroll
        for (int q = 0; q < 4; ++q) {
#pragma unroll
            for (int i = 0; i < 12; ++i) {
                int off = q * 24576 + (tid + i * RTH) * 16;
                cp16(h_s32 + off, hbc + off, true);
            }
            CP_COMMIT();
        }

        float acc[4][3];
        {
            int colb = gi * HH + n0 + jb;
#pragma unroll
            for (int mi = 0; mi < 4; ++mi) {
                const float* xrow = &xp[((size_t)(b0 + mi) * SS + t) * FOURH + colb];
                acc[mi][0] = __ldg(xrow + 0);
                acc[mi][1] = __ldg(xrow + 1);
                acc[mi][2] = __ldg(xrow + 2);
            }
        }

#pragma unroll
        for (int q = 0; q < 4; ++q) {
            if      (q == 0) CP_WAIT(3);
            else if (q == 1) CP_WAIT(2);
            else if (q == 2) CP_WAIT(1);
            else             CP_WAIT(0);
            __syncthreads();
            int k0 = q * 96, k1 = k0 + 96;
#pragma unroll 4
            for (int k = k0; k < k1; ++k) {
                float4 hv = *(const float4*)(h_s + k * BB + b0);
                const float* wr = W_s + k * RR + r0;
                float w0 = wr[0], w1 = wr[1], w2 = wr[2];
                acc[0][0] = fmaf(hv.x, w0, acc[0][0]);
                acc[1][0] = fmaf(hv.y, w0, acc[1][0]);
                acc[2][0] = fmaf(hv.z, w0, acc[2][0]);
                acc[3][0] = fmaf(hv.w, w0, acc[3][0]);
                acc[0][1] = fmaf(hv.x, w1, acc[0][1]);
                acc[1][1] = fmaf(hv.y, w1, acc[1][1]);
                acc[2][1] = fmaf(hv.z, w1, acc[2][1]);
                acc[3][1] = fmaf(hv.w, w1, acc[3][1]);
                acc[0][2] = fmaf(hv.x, w2, acc[0][2]);
                acc[1][2] = fmaf(hv.y, w2, acc[1][2]);
                acc[2][2] = fmaf(hv.z, w2, acc[2][2]);
                acc[3][2] = fmaf(hv.w, w2, acc[3][2]);
            }
        }

#pragma unroll
        for (int ni = 0; ni < 3; ++ni) {
            *(float4*)&gates_s[(r0 + ni) * BB + b0] =
                make_float4(acc[0][ni], acc[1][ni], acc[2][ni], acc[3][ni]);
        }
        __syncthreads();

#pragma unroll
        for (int u = 0; u < 3; ++u) {
            int idx = tid + u * RTH;           // 0..383
            int j = idx >> 6, b = idx & 63;
            float ig = gates_s[(0 * CH + j) * BB + b];
            float fg = gates_s[(1 * CH + j) * BB + b];
            float gg = gates_s[(2 * CH + j) * BB + b];
            float og = gates_s[(3 * CH + j) * BB + b];
            float c  = c_s[idx];
            c = sigf(fg) * c + sigf(ig) * tanhfast(gg);
            float h = sigf(og) * tanhfast(c);
            c_s[idx] = c;
            __stcg(&hb[(n0 + j) * BB + b], h);
            __nv_bfloat16 hh = __float2bfloat16(h);
            size_t fo = ((size_t)b * SS + t) * K2H + dir * HH + n0 + j;
            g_f1hi[fo] = hh;
            g_f1lo[fo] = __float2bfloat16(h - __bfloat162float(hh));
        }

        __threadfence();
        __syncthreads();
        if (tid == 0) {
            atomicAdd(&g_bar[dir][s], 1u);
            while (*(volatile unsigned*)&g_bar[dir][s] < (unsigned)NCD) { }
        }
        __syncthreads();
    }
}

// ---------------- launcher ----------------
extern "C" void kernel_launch(void* const* d_in, const int* in_sizes, int n_in,
                              void* d_out, int out_size)
{
    const float* f0     = (const float*)d_in[0];
    const int*   counts = (const int*)  d_in[1];
    const float* Wih_f  = (const float*)d_in[2];
    const float* Whh_f  = (const float*)d_in[3];
    const float* bih_f  = (const float*)d_in[4];
    const float* bhh_f  = (const float*)d_in[5];
    const float* Wih_b  = (const float*)d_in[6];
    const float* Whh_b  = (const float*)d_in[7];
    const float* bih_b  = (const float*)d_in[8];
    const float* bhh_b  = (const float*)d_in[9];
    const float* Wlin   = (const float*)d_in[10];
    const float* blin   = (const float*)d_in[11];
    float* out = (float*)d_out;

    void* p;
    cudaGetSymbolAddress(&p, g_xhi);     __nv_bfloat16* xhi = (__nv_bfloat16*)p;
    cudaGetSymbolAddress(&p, g_xlo);     __nv_bfloat16* xlo = (__nv_bfloat16*)p;
    cudaGetSymbolAddress(&p, g_xpf);     float* gxpf = (float*)p;
    cudaGetSymbolAddress(&p, g_xpb);     float* gxpb = (float*)p;
    cudaGetSymbolAddress(&p, g_f1hi);    __nv_bfloat16* f1hi = (__nv_bfloat16*)p;
    cudaGetSymbolAddress(&p, g_f1lo);    __nv_bfloat16* f1lo = (__nv_bfloat16*)p;
    cudaGetSymbolAddress(&p, g_wihf_hi); __nv_bfloat16* wfh = (__nv_bfloat16*)p;
    cudaGetSymbolAddress(&p, g_wihf_lo); __nv_bfloat16* wfl = (__nv_bfloat16*)p;
    cudaGetSymbolAddress(&p, g_wihb_hi); __nv_bfloat16* wbh = (__nv_bfloat16*)p;
    cudaGetSymbolAddress(&p, g_wihb_lo); __nv_bfloat16* wbl = (__nv_bfloat16*)p;
    cudaGetSymbolAddress(&p, g_wlin_hi); __nv_bfloat16* wlh = (__nv_bfloat16*)p;
    cudaGetSymbolAddress(&p, g_wlin_lo); __nv_bfloat16* wll = (__nv_bfloat16*)p;

    const int lstm_smem = (HH * BB + HH * RR + RR * BB + CH * BB) * (int)sizeof(float);
    cudaFuncSetAttribute(lstm_kernel, cudaFuncAttributeMaxDynamicSharedMemorySize, lstm_smem);
    cudaFuncSetAttribute(gemm3_kernel, cudaFuncAttributeMaxDynamicSharedMemorySize, 2 * STGB);

    init_kernel<<<2, 256>>>();
    pool_kernel<<<BB, 256>>>(f0, counts, xhi, xlo);

    int nw = FOURH * DD;
    cvt_kernel<<<(nw + 255) / 256, 256>>>(Wih_f, wfh, wfl, nw);
    cvt_kernel<<<(nw + 255) / 256, 256>>>(Wih_b, wbh, wbl, nw);
    int nl = CC * K2H;
    cvt_kernel<<<(nl + 255) / 256, 256>>>(Wlin, wlh, wll, nl);

    dim3 gproj(FOURH / 128, MM / 128);   // 12 x 256
    gemm3_kernel<<<gproj, 256, 2 * STGB>>>(xhi, xlo, wfh, wfl, bih_f, bhh_f, gxpf, FOURH, DD);
    gemm3_kernel<<<gproj, 256, 2 * STGB>>>(xhi, xlo, wbh, wbl, bih_b, bhh_b, gxpb, FOURH, DD);

    lstm_kernel<<<2 * NCD, RTH, lstm_smem>>>(Whh_f, Whh_b);

    dim3 gout((CC + 127) / 128, MM / 128);  // 4 x 256
    gemm3_kernel<<<gout, 256, 2 * STGB>>>(f1hi, f1lo, wlh, wll, blin, nullptr, out, CC, K2H);
}

// round 6
// speedup vs baseline: 1.2518x; 1.2518x over previous
#include <cuda_runtime.h>
#include <cuda_bf16.h>
#include <math.h>
#include <stdint.h>

// Problem dims
#define BB   64
#define SS   512
#define DD   768
#define WW   256
#define HH   384
#define FOURH 1536
#define CC   425
#define K2H  768
#define MM   (BB*SS)      // 32768 rows

// Recurrence config
#define NCD   64          // CTAs per direction (128 total)
#define CH    6           // h-indices per CTA (64*6 = 384)
#define RR    24          // gate rows per CTA (4 gates * CH)
#define RTH   384         // 12 warps: 4 m-tiles x 3 n-tiles

// -------- scratch (device globals; no allocation allowed) --------
__device__ __nv_bfloat16 g_xhi[MM * DD];
__device__ __nv_bfloat16 g_xlo[MM * DD];
__device__ float g_xpf[MM * FOURH];
__device__ float g_xpb[MM * FOURH];
__device__ __nv_bfloat16 g_f1hi[MM * K2H];
__device__ __nv_bfloat16 g_f1lo[MM * K2H];
__device__ __nv_bfloat16 g_hbhi[2][2][BB * HH];   // [dir][parity][b*384+k]
__device__ __nv_bfloat16 g_hblo[2][2][BB * HH];
__device__ unsigned g_bar[2][SS][8];              // split barrier counters
__device__ __nv_bfloat16 g_wihf_hi[FOURH * DD], g_wihf_lo[FOURH * DD];
__device__ __nv_bfloat16 g_wihb_hi[FOURH * DD], g_wihb_lo[FOURH * DD];
__device__ __nv_bfloat16 g_wlin_hi[CC * K2H],  g_wlin_lo[CC * K2H];

// ---------------- small helpers ----------------
__device__ __forceinline__ uint32_t smem_u32(const void* p) {
    uint32_t a;
    asm("{ .reg .u64 t; cvta.to.shared.u64 t, %1; cvt.u32.u64 %0, t; }"
        : "=r"(a) : "l"(p));
    return a;
}
__device__ __forceinline__ void cp16(uint32_t d, const void* s, bool v) {
    int sz = v ? 16 : 0;
    asm volatile("cp.async.cg.shared.global [%0], [%1], 16, %2;\n"
                 :: "r"(d), "l"(s), "r"(sz));
}
#define CP_COMMIT() asm volatile("cp.async.commit_group;\n")
#define CP_WAIT(n)  asm volatile("cp.async.wait_group %0;\n" :: "n"(n))

#define LDM4(r, addr) \
    asm volatile("ldmatrix.sync.aligned.m8n8.x4.shared.b16 {%0,%1,%2,%3}, [%4];" \
        : "=r"((r)[0]), "=r"((r)[1]), "=r"((r)[2]), "=r"((r)[3]) : "r"(addr))
#define LDM2(r, addr) \
    asm volatile("ldmatrix.sync.aligned.m8n8.x2.shared.b16 {%0,%1}, [%2];" \
        : "=r"((r)[0]), "=r"((r)[1]) : "r"(addr))

#define MMA(d, a, b0, b1) \
    asm volatile("mma.sync.aligned.m16n8k16.row.col.f32.bf16.bf16.f32 " \
        "{%0,%1,%2,%3},{%4,%5,%6,%7},{%8,%9},{%0,%1,%2,%3};" \
        : "+f"((d)[0]), "+f"((d)[1]), "+f"((d)[2]), "+f"((d)[3]) \
        : "r"((a)[0]), "r"((a)[1]), "r"((a)[2]), "r"((a)[3]), "r"(b0), "r"(b1))

// fast activations (clamped; rel err ~1e-6)
__device__ __forceinline__ float sigf(float x) {
    x = fminf(fmaxf(x, -30.0f), 30.0f);
    return __fdividef(1.0f, 1.0f + __expf(-x));
}
__device__ __forceinline__ float tanhfast(float x) {
    x = fminf(fmaxf(x, -15.0f), 15.0f);
    float e = __expf(2.0f * x);
    return __fdividef(e - 1.0f, e + 1.0f);
}

// ---------------- init: zero state + barriers (every replay) ----------------
__global__ void init_kernel()
{
    int tid = threadIdx.x + blockIdx.x * blockDim.x;
    int nt  = blockDim.x * gridDim.x;
    for (int i = tid; i < 2 * BB * HH; i += nt) {        // parity-0 buffers
        g_hbhi[i / (BB * HH)][0][i % (BB * HH)] = __float2bfloat16(0.0f);
        g_hblo[i / (BB * HH)][0][i % (BB * HH)] = __float2bfloat16(0.0f);
    }
    unsigned* bp = &g_bar[0][0][0];
    for (int i = tid; i < 2 * SS * 8; i += nt) bp[i] = 0u;
}

// ---------------- fp32 -> (hi, lo) bf16 split ----------------
__global__ void cvt_kernel(const float* __restrict__ in,
                           __nv_bfloat16* __restrict__ hi,
                           __nv_bfloat16* __restrict__ lo, int n)
{
    int i = blockIdx.x * blockDim.x + threadIdx.x;
    if (i < n) {
        float v = in[i];
        __nv_bfloat16 h = __float2bfloat16(v);
        hi[i] = h;
        lo[i] = __float2bfloat16(v - __bfloat162float(h));
    }
}

// ---------------- segment mean pool (writes split bf16) ----------------
__global__ void pool_kernel(const float* __restrict__ f0,
                            const int*   __restrict__ counts,
                            __nv_bfloat16* __restrict__ xhi,
                            __nv_bfloat16* __restrict__ xlo)
{
    __shared__ int s_start[WW];
    __shared__ int s_cnt[WW];
    int b = blockIdx.x;
    int tid = threadIdx.x;
    if (tid == 0) {
        int run = 0;
        for (int j = 0; j < WW; ++j) {
            int c = counts[b * WW + j];
            s_start[j] = run; s_cnt[j] = c; run += c;
        }
    }
    __syncthreads();
    const float* fb = f0 + (size_t)b * SS * DD;
    __nv_bfloat16* xh = xhi + (size_t)b * SS * DD;
    __nv_bfloat16* xl = xlo + (size_t)b * SS * DD;
    for (int idx = tid; idx < WW * DD; idx += blockDim.x) {
        int j = idx / DD, d = idx - j * DD;
        int st = s_start[j], c = s_cnt[j];
        float v = 0.0f;
        for (int p = 0; p < c; ++p) v += fb[(size_t)(st + p) * DD + d];
        v /= (float)c;
        __nv_bfloat16 h = __float2bfloat16(v);
        xh[idx] = h;
        xl[idx] = __float2bfloat16(v - __bfloat162float(h));
    }
    for (int idx = tid; idx < (SS - WW) * DD; idx += blockDim.x) {
        float v = fb[WW * DD + idx];
        __nv_bfloat16 h = __float2bfloat16(v);
        xh[WW * DD + idx] = h;
        xl[WW * DD + idx] = __float2bfloat16(v - __bfloat162float(h));
    }
}

// ---------------- split-bf16 tensor-core GEMM (mma.sync) ----------------
#define ARRB  (128 * 80)
#define STGB  (4 * ARRB)

__global__ void __launch_bounds__(256, 1)
gemm3_kernel(const __nv_bfloat16* __restrict__ Ahi, const __nv_bfloat16* __restrict__ Alo,
             const __nv_bfloat16* __restrict__ Bhi, const __nv_bfloat16* __restrict__ Blo,
             const float* __restrict__ bias1, const float* __restrict__ bias2,
             float* __restrict__ C, int N, int K)
{
    extern __shared__ char smem[];
    uint32_t sb = smem_u32(smem);
    int tid = threadIdx.x, lane = tid & 31, wid = tid >> 5;
    int wm = wid >> 2, wn = wid & 3;
    int bm = blockIdx.y, bn = blockIdx.x;

    int lr = tid >> 1;
    int lc = (tid & 1) * 2;
    int arow = bm * 128 + lr;
    int brow = bn * 128 + lr;
    bool bv  = brow < N;
    const __nv_bfloat16* pAh = Ahi + (size_t)arow * K;
    const __nv_bfloat16* pAl = Alo + (size_t)arow * K;
    const __nv_bfloat16* pBh = Bhi + (size_t)(bv ? brow : 0) * K;
    const __nv_bfloat16* pBl = Blo + (size_t)(bv ? brow : 0) * K;
    uint32_t sd = sb + lr * 80 + lc * 16;

    float acc[4][4][4];
#pragma unroll
    for (int a = 0; a < 4; ++a)
#pragma unroll
        for (int b = 0; b < 4; ++b)
#pragma unroll
            for (int c = 0; c < 4; ++c) acc[a][b][c] = 0.0f;

    int KT = K >> 5;

    {
        uint32_t d = sd;
#pragma unroll
        for (int cc = 0; cc < 2; ++cc) {
            cp16(d + cc * 16 + 0 * ARRB, pAh + (lc + cc) * 8, true);
            cp16(d + cc * 16 + 1 * ARRB, pAl + (lc + cc) * 8, true);
            cp16(d + cc * 16 + 2 * ARRB, pBh + (lc + cc) * 8, bv);
            cp16(d + cc * 16 + 3 * ARRB, pBl + (lc + cc) * 8, bv);
        }
        CP_COMMIT();
    }

    int la  = lane & 15, lc4 = lane >> 4;
    int lb  = (lane & 7) + ((lane & 16) >> 1);
    int lbc = (lane >> 3) & 1;

    for (int i = 0; i < KT; ++i) {
        CP_WAIT(0);
        __syncthreads();
        if (i + 1 < KT) {
            int ko = (i + 1) << 5;
            uint32_t d = sd + ((i + 1) & 1) * STGB;
#pragma unroll
            for (int cc = 0; cc < 2; ++cc) {
                cp16(d + cc * 16 + 0 * ARRB, pAh + ko + (lc + cc) * 8, true);
                cp16(d + cc * 16 + 1 * ARRB, pAl + ko + (lc + cc) * 8, true);
                cp16(d + cc * 16 + 2 * ARRB, pBh + ko + (lc + cc) * 8, bv);
                cp16(d + cc * 16 + 3 * ARRB, pBl + ko + (lc + cc) * 8, bv);
            }
            CP_COMMIT();
        }
        uint32_t st = sb + (i & 1) * STGB;
#pragma unroll
        for (int kh = 0; kh < 2; ++kh) {
            uint32_t aaddr = st + (wm * 64 + la) * 80 + (kh * 2 + lc4) * 16;
            uint32_t ah[4][4], al[4][4];
#pragma unroll
            for (int mt = 0; mt < 4; ++mt) {
                LDM4(ah[mt], aaddr + mt * 1280);
                LDM4(al[mt], aaddr + mt * 1280 + ARRB);
            }
            uint32_t bbase = st + 2 * ARRB + (wn * 32 + lb) * 80 + (kh * 2 + lbc) * 16;
            uint32_t bh[2][4], bl[2][4];
#pragma unroll
            for (int ntp = 0; ntp < 2; ++ntp) {
                LDM4(bh[ntp], bbase + ntp * 1280);
                LDM4(bl[ntp], bbase + ntp * 1280 + ARRB);
            }
#pragma unroll
            for (int mt = 0; mt < 4; ++mt)
#pragma unroll
                for (int ntp = 0; ntp < 2; ++ntp) {
                    MMA(acc[mt][2 * ntp + 0], ah[mt], bh[ntp][0], bh[ntp][1]);
                    MMA(acc[mt][2 * ntp + 1], ah[mt], bh[ntp][2], bh[ntp][3]);
                }
#pragma unroll
            for (int mt = 0; mt < 4; ++mt)
#pragma unroll
                for (int ntp = 0; ntp < 2; ++ntp) {
                    MMA(acc[mt][2 * ntp + 0], ah[mt], bl[ntp][0], bl[ntp][1]);
                    MMA(acc[mt][2 * ntp + 1], ah[mt], bl[ntp][2], bl[ntp][3]);
                }
#pragma unroll
            for (int mt = 0; mt < 4; ++mt)
#pragma unroll
                for (int ntp = 0; ntp < 2; ++ntp) {
                    MMA(acc[mt][2 * ntp + 0], al[mt], bh[ntp][0], bh[ntp][1]);
                    MMA(acc[mt][2 * ntp + 1], al[mt], bh[ntp][2], bh[ntp][3]);
                }
        }
        __syncthreads();
    }

#pragma unroll
    for (int mt = 0; mt < 4; ++mt) {
        int m0 = bm * 128 + wm * 64 + mt * 16 + (lane >> 2);
#pragma unroll
        for (int nt = 0; nt < 4; ++nt) {
            int n0 = bn * 128 + wn * 32 + nt * 8 + (lane & 3) * 2;
            float* a = acc[mt][nt];
            if (n0 < N) {
                float bs = bias1[n0] + (bias2 ? bias2[n0] : 0.0f);
                C[(size_t)m0 * N + n0]       = a[0] + bs;
                C[(size_t)(m0 + 8) * N + n0] = a[2] + bs;
            }
            if (n0 + 1 < N) {
                float bs = bias1[n0 + 1] + (bias2 ? bias2[n0 + 1] : 0.0f);
                C[(size_t)m0 * N + n0 + 1]       = a[1] + bs;
                C[(size_t)(m0 + 8) * N + n0 + 1] = a[3] + bs;
            }
        }
    }
}

// ---------------- persistent tensor-core LSTM recurrence ----------------
// 128 CTAs (64/dir), 384 threads = 12 warps, warp (wid&3, wid>>2) owns
// (m16, n8) tile of the [64 x 24] gate GEMM, split-bf16 3-term on mma.sync.
// h exchanged as bf16 hi/lo, double-buffered by step parity.
// SMEM layout (bytes):
#define LA_HI   0
#define LA_LO   50176           // 64 rows * 784B pitch
#define LW_HI   100352
#define LW_LO   119168          // 24 rows * 784B
#define LGATES  137984          // 64 * 26 floats
#define LCS     144640          // 384 floats
#define LSMEM   146176
#define PITCH   784

__global__ void __launch_bounds__(RTH, 1)
lstm_kernel(const float* __restrict__ Whh_f, const float* __restrict__ Whh_b)
{
    extern __shared__ char smem[];
    uint32_t sb = smem_u32(smem);
    float* gates_s = (float*)(smem + LGATES);
    float* c_s     = (float*)(smem + LCS);

    int cta = blockIdx.x;
    int dir = (cta >= NCD) ? 1 : 0;
    int ci  = cta - dir * NCD;
    const float* Whh = dir ? Whh_b : Whh_f;
    const float* xp  = dir ? g_xpb : g_xpf;
    int n0  = ci * CH;
    int tid = threadIdx.x;
    int lane = tid & 31, wid = tid >> 5;
    int mt = wid & 3;          // m-tile (16 b rows)
    int nt = wid >> 2;         // n-tile (8 gate rows)

    // ---- load + split Whh slice into SMEM (once) ----
    for (int idx = tid; idx < RR * HH; idx += RTH) {
        int r = idx / HH, k = idx - r * HH;
        int gi = r / CH, j = r - gi * CH;
        float v = Whh[(size_t)(gi * HH + n0 + j) * HH + k];
        __nv_bfloat16 h = __float2bfloat16(v);
        *(__nv_bfloat16*)(smem + LW_HI + r * PITCH + k * 2) = h;
        *(__nv_bfloat16*)(smem + LW_LO + r * PITCH + k * 2) =
            __float2bfloat16(v - __bfloat162float(h));
    }
    for (int idx = tid; idx < CH * BB; idx += RTH) c_s[idx] = 0.0f;
    __syncthreads();

    // cell-update mapping: this thread owns cell (j, b)
    int cj = tid >> 6;         // 0..5
    int cb = tid & 63;

    // ldmatrix address components
    int la  = lane & 15, lc4 = lane >> 4;
    uint32_t aAddrBase = sb + LA_HI + (mt * 16 + la) * PITCH + lc4 * 16;
    uint32_t bAddrBase = sb + LW_HI + (nt * 8 + (lane & 7)) * PITCH + ((lane >> 3) & 1) * 16;

    // initial xp prefetch for step 0
    float xg[4];
    {
        int t0 = dir ? (SS - 1) : 0;
        const float* xr = &xp[((size_t)cb * SS + t0) * FOURH + n0 + cj];
#pragma unroll
        for (int gi = 0; gi < 4; ++gi) xg[gi] = __ldg(xr + gi * HH);
    }

    for (int s = 0; s < SS; ++s) {
        int t = dir ? (SS - 1 - s) : s;
        int p = s & 1;

        // ---- issue h copy: 4 chunks x (hi+lo), 4 cp16/thread/chunk ----
        const char* srcH = (const char*)&g_hbhi[dir][p][0];
        const char* srcL = (const char*)&g_hblo[dir][p][0];
#pragma unroll
        for (int q = 0; q < 4; ++q) {
#pragma unroll
            for (int i = 0; i < 2; ++i) {
                int e = i * RTH + tid;            // 0..767
                int row = e / 12, cc = e - row * 12;
                uint32_t so = row * 768 + q * 192 + cc * 16;
                uint32_t doff = row * PITCH + q * 192 + cc * 16;
                cp16(sb + LA_HI + doff, srcH + so, true);
                cp16(sb + LA_LO + doff, srcL + so, true);
            }
            CP_COMMIT();
        }

        // ---- gate GEMM: 24 k16 steps in 4 chunks ----
        float acc[4] = {0.f, 0.f, 0.f, 0.f};
#pragma unroll
        for (int q = 0; q < 4; ++q) {
            if      (q == 0) CP_WAIT(3);
            else if (q == 1) CP_WAIT(2);
            else if (q == 2) CP_WAIT(1);
            else             CP_WAIT(0);
            __syncthreads();
#pragma unroll
            for (int kk = 0; kk < 6; ++kk) {
                int k16 = q * 6 + kk;
                uint32_t ka = aAddrBase + k16 * 32;
                uint32_t kb = bAddrBase + k16 * 32;
                uint32_t ah[4], al[4], bh[2], bl[2];
                LDM4(ah, ka);
                LDM4(al, ka + (LA_LO - LA_HI));
                LDM2(bh, kb);
                LDM2(bl, kb + (LW_LO - LW_HI));
                MMA(acc, ah, bh[0], bh[1]);
                MMA(acc, ah, bl[0], bl[1]);
                MMA(acc, al, bh[0], bh[1]);
            }
        }

        // ---- epilogue: store gates to SMEM [b][r], pitch 26 ----
        {
            int brow = mt * 16 + (lane >> 2);
            int rcol = nt * 8 + (lane & 3) * 2;
            *(float2*)&gates_s[brow * 26 + rcol]       = make_float2(acc[0], acc[1]);
            *(float2*)&gates_s[(brow + 8) * 26 + rcol] = make_float2(acc[2], acc[3]);
        }
        __syncthreads();

        // ---- cell update (1 cell per thread) ----
        {
            float ig = gates_s[cb * 26 + 0 * CH + cj] + xg[0];
            float fg = gates_s[cb * 26 + 1 * CH + cj] + xg[1];
            float gg = gates_s[cb * 26 + 2 * CH + cj] + xg[2];
            float og = gates_s[cb * 26 + 3 * CH + cj] + xg[3];
            float c  = c_s[tid];
            c = sigf(fg) * c + sigf(ig) * tanhfast(gg);
            float h = sigf(og) * tanhfast(c);
            c_s[tid] = c;
            __nv_bfloat16 hh = __float2bfloat16(h);
            __nv_bfloat16 hl = __float2bfloat16(h - __bfloat162float(hh));
            int np = (s + 1) & 1;
            g_hbhi[dir][np][cb * HH + n0 + cj] = hh;
            g_hblo[dir][np][cb * HH + n0 + cj] = hl;
            size_t fo = ((size_t)cb * SS + t) * K2H + dir * HH + n0 + cj;
            g_f1hi[fo] = hh;
            g_f1lo[fo] = hl;
        }

        // ---- prefetch xp for next step (hidden under barrier) ----
        if (s + 1 < SS) {
            int t1 = dir ? (SS - 2 - s) : (s + 1);
            const float* xr = &xp[((size_t)cb * SS + t1) * FOURH + n0 + cj];
#pragma unroll
            for (int gi = 0; gi < 4; ++gi) xg[gi] = __ldg(xr + gi * HH);
        }

        // ---- inter-CTA barrier (split counters) ----
        __threadfence();
        __syncthreads();
        if (tid == 0) {
            atomicAdd(&g_bar[dir][s][ci & 7], 1u);
            const volatile unsigned* bw = &g_bar[dir][s][0];
            unsigned sum;
            do {
                sum = bw[0] + bw[1] + bw[2] + bw[3] + bw[4] + bw[5] + bw[6] + bw[7];
            } while (sum < (unsigned)NCD);
        }
        __syncthreads();
    }
}

// ---------------- launcher ----------------
extern "C" void kernel_launch(void* const* d_in, const int* in_sizes, int n_in,
                              void* d_out, int out_size)
{
    const float* f0     = (const float*)d_in[0];
    const int*   counts = (const int*)  d_in[1];
    const float* Wih_f  = (const float*)d_in[2];
    const float* Whh_f  = (const float*)d_in[3];
    const float* bih_f  = (const float*)d_in[4];
    const float* bhh_f  = (const float*)d_in[5];
    const float* Wih_b  = (const float*)d_in[6];
    const float* Whh_b  = (const float*)d_in[7];
    const float* bih_b  = (const float*)d_in[8];
    const float* bhh_b  = (const float*)d_in[9];
    const float* Wlin   = (const float*)d_in[10];
    const float* blin   = (const float*)d_in[11];
    float* out = (float*)d_out;

    void* p;
    cudaGetSymbolAddress(&p, g_xhi);     __nv_bfloat16* xhi = (__nv_bfloat16*)p;
    cudaGetSymbolAddress(&p, g_xlo);     __nv_bfloat16* xlo = (__nv_bfloat16*)p;
    cudaGetSymbolAddress(&p, g_xpf);     float* gxpf = (float*)p;
    cudaGetSymbolAddress(&p, g_xpb);     float* gxpb = (float*)p;
    cudaGetSymbolAddress(&p, g_f1hi);    __nv_bfloat16* f1hi = (__nv_bfloat16*)p;
    cudaGetSymbolAddress(&p, g_f1lo);    __nv_bfloat16* f1lo = (__nv_bfloat16*)p;
    cudaGetSymbolAddress(&p, g_wihf_hi); __nv_bfloat16* wfh = (__nv_bfloat16*)p;
    cudaGetSymbolAddress(&p, g_wihf_lo); __nv_bfloat16* wfl = (__nv_bfloat16*)p;
    cudaGetSymbolAddress(&p, g_wihb_hi); __nv_bfloat16* wbh = (__nv_bfloat16*)p;
    cudaGetSymbolAddress(&p, g_wihb_lo); __nv_bfloat16* wbl = (__nv_bfloat16*)p;
    cudaGetSymbolAddress(&p, g_wlin_hi); __nv_bfloat16* wlh = (__nv_bfloat16*)p;
    cudaGetSymbolAddress(&p, g_wlin_lo); __nv_bfloat16* wll = (__nv_bfloat16*)p;

    cudaFuncSetAttribute(lstm_kernel, cudaFuncAttributeMaxDynamicSharedMemorySize, LSMEM);
    cudaFuncSetAttribute(gemm3_kernel, cudaFuncAttributeMaxDynamicSharedMemorySize, 2 * STGB);

    init_kernel<<<4, 256>>>();
    pool_kernel<<<BB, 256>>>(f0, counts, xhi, xlo);

    int nw = FOURH * DD;
    cvt_kernel<<<(nw + 255) / 256, 256>>>(Wih_f, wfh, wfl, nw);
    cvt_kernel<<<(nw + 255) / 256, 256>>>(Wih_b, wbh, wbl, nw);
    int nl = CC * K2H;
    cvt_kernel<<<(nl + 255) / 256, 256>>>(Wlin, wlh, wll, nl);

    dim3 gproj(FOURH / 128, MM / 128);   // 12 x 256
    gemm3_kernel<<<gproj, 256, 2 * STGB>>>(xhi, xlo, wfh, wfl, bih_f, bhh_f, gxpf, FOURH, DD);
    gemm3_kernel<<<gproj, 256, 2 * STGB>>>(xhi, xlo, wbh, wbl, bih_b, bhh_b, gxpb, FOURH, DD);

    lstm_kernel<<<2 * NCD, RTH, LSMEM>>>(Whh_f, Whh_b);

    dim3 gout((CC + 127) / 128, MM / 128);  // 4 x 256
    gemm3_kernel<<<gout, 256, 2 * STGB>>>(f1hi, f1lo, wlh, wll, blin, nullptr, out, CC, K2H);
}

// round 8
// speedup vs baseline: 1.2529x; 1.0008x over previous
#include <cuda_runtime.h>
#include <cuda_bf16.h>
#include <math.h>
#include <stdint.h>

// Problem dims
#define BB   64
#define SS   512
#define DD   768
#define WW   256
#define HH   384
#define FOURH 1536
#define CC   425
#define K2H  768
#define MM   (BB*SS)      // 32768 rows

// Recurrence config
#define NCD   64          // CTAs per direction (128 total)
#define CH    6           // h-indices per CTA (64*6 = 384)
#define RR    24          // gate rows per CTA (4 gates * CH)
#define RTH   384         // 12 warps: 4 m-tiles x 3 n-tiles

// -------- scratch (device globals; no allocation allowed) --------
__device__ __nv_bfloat16 g_xhi[MM * DD];
__device__ __nv_bfloat16 g_xlo[MM * DD];
__device__ float g_xpf[MM * FOURH];
__device__ float g_xpb[MM * FOURH];
__device__ __nv_bfloat16 g_f1hi[MM * K2H];
__device__ __nv_bfloat16 g_f1lo[MM * K2H];
__device__ __nv_bfloat16 g_hbhi[2][2][BB * HH];   // [dir][parity][b*384+k]
__device__ __nv_bfloat16 g_hblo[2][2][BB * HH];
__device__ unsigned g_bar[2][SS][8];              // split barrier counters
__device__ __nv_bfloat16 g_wihf_hi[FOURH * DD], g_wihf_lo[FOURH * DD];
__device__ __nv_bfloat16 g_wihb_hi[FOURH * DD], g_wihb_lo[FOURH * DD];
__device__ __nv_bfloat16 g_wlin_hi[CC * K2H],  g_wlin_lo[CC * K2H];

// ---------------- small helpers ----------------
__device__ __forceinline__ uint32_t smem_u32(const void* p) {
    uint32_t a;
    asm("{ .reg .u64 t; cvta.to.shared.u64 t, %1; cvt.u32.u64 %0, t; }"
        : "=r"(a) : "l"(p));
    return a;
}
__device__ __forceinline__ void cp16(uint32_t d, const void* s, bool v) {
    int sz = v ? 16 : 0;
    asm volatile("cp.async.cg.shared.global [%0], [%1], 16, %2;\n"
                 :: "r"(d), "l"(s), "r"(sz));
}
#define CP_COMMIT() asm volatile("cp.async.commit_group;\n")
#define CP_WAIT(n)  asm volatile("cp.async.wait_group %0;\n" :: "n"(n))

#define LDM4(r, addr) \
    asm volatile("ldmatrix.sync.aligned.m8n8.x4.shared.b16 {%0,%1,%2,%3}, [%4];" \
        : "=r"((r)[0]), "=r"((r)[1]), "=r"((r)[2]), "=r"((r)[3]) : "r"(addr))
#define LDM2(r, addr) \
    asm volatile("ldmatrix.sync.aligned.m8n8.x2.shared.b16 {%0,%1}, [%2];" \
        : "=r"((r)[0]), "=r"((r)[1]) : "r"(addr))

#define MMA(d, a, b0, b1) \
    asm volatile("mma.sync.aligned.m16n8k16.row.col.f32.bf16.bf16.f32 " \
        "{%0,%1,%2,%3},{%4,%5,%6,%7},{%8,%9},{%0,%1,%2,%3};" \
        : "+f"((d)[0]), "+f"((d)[1]), "+f"((d)[2]), "+f"((d)[3]) \
        : "r"((a)[0]), "r"((a)[1]), "r"((a)[2]), "r"((a)[3]), "r"(b0), "r"(b1))

// fast activations (clamped; rel err ~1e-6)
__device__ __forceinline__ float sigf(float x) {
    x = fminf(fmaxf(x, -30.0f), 30.0f);
    return __fdividef(1.0f, 1.0f + __expf(-x));
}
__device__ __forceinline__ float tanhfast(float x) {
    x = fminf(fmaxf(x, -15.0f), 15.0f);
    float e = __expf(2.0f * x);
    return __fdividef(e - 1.0f, e + 1.0f);
}

// ---------------- init: zero state + barriers (every replay) ----------------
__global__ void init_kernel()
{
    int tid = threadIdx.x + blockIdx.x * blockDim.x;
    int nt  = blockDim.x * gridDim.x;
    for (int i = tid; i < 2 * BB * HH; i += nt) {        // parity-0 buffers
        g_hbhi[i / (BB * HH)][0][i % (BB * HH)] = __float2bfloat16(0.0f);
        g_hblo[i / (BB * HH)][0][i % (BB * HH)] = __float2bfloat16(0.0f);
    }
    unsigned* bp = &g_bar[0][0][0];
    for (int i = tid; i < 2 * SS * 8; i += nt) bp[i] = 0u;
}

// ---------------- fused fp32 -> (hi, lo) bf16 split for 3 weight tensors ----
__global__ void cvt3_kernel(const float* __restrict__ in0, __nv_bfloat16* __restrict__ hi0,
                            __nv_bfloat16* __restrict__ lo0, int n0,
                            const float* __restrict__ in1, __nv_bfloat16* __restrict__ hi1,
                            __nv_bfloat16* __restrict__ lo1, int n1,
                            const float* __restrict__ in2, __nv_bfloat16* __restrict__ hi2,
                            __nv_bfloat16* __restrict__ lo2, int n2)
{
    int i = blockIdx.x * blockDim.x + threadIdx.x;
    const float* in; __nv_bfloat16 *hi, *lo;
    if (i < n0)           { in = in0; hi = hi0; lo = lo0; }
    else if (i < n0 + n1) { i -= n0; in = in1; hi = hi1; lo = lo1; }
    else if (i < n0 + n1 + n2) { i -= n0 + n1; in = in2; hi = hi2; lo = lo2; }
    else return;
    float v = in[i];
    __nv_bfloat16 h = __float2bfloat16(v);
    hi[i] = h;
    lo[i] = __float2bfloat16(v - __bfloat162float(h));
}

// ---------------- segment mean pool (writes split bf16) ----------------
__global__ void pool_kernel(const float* __restrict__ f0,
                            const int*   __restrict__ counts,
                            __nv_bfloat16* __restrict__ xhi,
                            __nv_bfloat16* __restrict__ xlo)
{
    __shared__ int s_start[WW];
    __shared__ int s_cnt[WW];
    int b = blockIdx.x;
    int tid = threadIdx.x;
    if (tid == 0) {
        int run = 0;
        for (int j = 0; j < WW; ++j) {
            int c = counts[b * WW + j];
            s_start[j] = run; s_cnt[j] = c; run += c;
        }
    }
    __syncthreads();
    const float* fb = f0 + (size_t)b * SS * DD;
    __nv_bfloat16* xh = xhi + (size_t)b * SS * DD;
    __nv_bfloat16* xl = xlo + (size_t)b * SS * DD;
    for (int idx = tid; idx < WW * DD; idx += blockDim.x) {
        int j = idx / DD, d = idx - j * DD;
        int st = s_start[j], c = s_cnt[j];
        float v = 0.0f;
        for (int p = 0; p < c; ++p) v += fb[(size_t)(st + p) * DD + d];
        v /= (float)c;
        __nv_bfloat16 h = __float2bfloat16(v);
        xh[idx] = h;
        xl[idx] = __float2bfloat16(v - __bfloat162float(h));
    }
    for (int idx = tid; idx < (SS - WW) * DD; idx += blockDim.x) {
        float v = fb[WW * DD + idx];
        __nv_bfloat16 h = __float2bfloat16(v);
        xh[WW * DD + idx] = h;
        xl[WW * DD + idx] = __float2bfloat16(v - __bfloat162float(h));
    }
}

// ---------------- split-bf16 tensor-core GEMM (mma.sync) ----------------
#define ARRB  (128 * 80)
#define STGB  (4 * ARRB)

__global__ void __launch_bounds__(256, 1)
gemm3_kernel(const __nv_bfloat16* __restrict__ Ahi, const __nv_bfloat16* __restrict__ Alo,
             const __nv_bfloat16* __restrict__ Bhi, const __nv_bfloat16* __restrict__ Blo,
             const float* __restrict__ bias1, const float* __restrict__ bias2,
             float* __restrict__ C, int N, int K)
{
    extern __shared__ char smem[];
    uint32_t sb = smem_u32(smem);
    int tid = threadIdx.x, lane = tid & 31, wid = tid >> 5;
    int wm = wid >> 2, wn = wid & 3;
    int bm = blockIdx.y, bn = blockIdx.x;

    int lr = tid >> 1;
    int lc = (tid & 1) * 2;
    int arow = bm * 128 + lr;
    int brow = bn * 128 + lr;
    bool bv  = brow < N;
    const __nv_bfloat16* pAh = Ahi + (size_t)arow * K;
    const __nv_bfloat16* pAl = Alo + (size_t)arow * K;
    const __nv_bfloat16* pBh = Bhi + (size_t)(bv ? brow : 0) * K;
    const __nv_bfloat16* pBl = Blo + (size_t)(bv ? brow : 0) * K;
    uint32_t sd = sb + lr * 80 + lc * 16;

    float acc[4][4][4];
#pragma unroll
    for (int a = 0; a < 4; ++a)
#pragma unroll
        for (int b = 0; b < 4; ++b)
#pragma unroll
            for (int c = 0; c < 4; ++c) acc[a][b][c] = 0.0f;

    int KT = K >> 5;

    {
        uint32_t d = sd;
#pragma unroll
        for (int cc = 0; cc < 2; ++cc) {
            cp16(d + cc * 16 + 0 * ARRB, pAh + (lc + cc) * 8, true);
            cp16(d + cc * 16 + 1 * ARRB, pAl + (lc + cc) * 8, true);
            cp16(d + cc * 16 + 2 * ARRB, pBh + (lc + cc) * 8, bv);
            cp16(d + cc * 16 + 3 * ARRB, pBl + (lc + cc) * 8, bv);
        }
        CP_COMMIT();
    }

    int la  = lane & 15, lc4 = lane >> 4;
    int lb  = (lane & 7) + ((lane & 16) >> 1);
    int lbc = (lane >> 3) & 1;

    for (int i = 0; i < KT; ++i) {
        CP_WAIT(0);
        __syncthreads();
        if (i + 1 < KT) {
            int ko = (i + 1) << 5;
            uint32_t d = sd + ((i + 1) & 1) * STGB;
#pragma unroll
            for (int cc = 0; cc < 2; ++cc) {
                cp16(d + cc * 16 + 0 * ARRB, pAh + ko + (lc + cc) * 8, true);
                cp16(d + cc * 16 + 1 * ARRB, pAl + ko + (lc + cc) * 8, true);
                cp16(d + cc * 16 + 2 * ARRB, pBh + ko + (lc + cc) * 8, bv);
                cp16(d + cc * 16 + 3 * ARRB, pBl + ko + (lc + cc) * 8, bv);
            }
            CP_COMMIT();
        }
        uint32_t st = sb + (i & 1) * STGB;
#pragma unroll
        for (int kh = 0; kh < 2; ++kh) {
            uint32_t aaddr = st + (wm * 64 + la) * 80 + (kh * 2 + lc4) * 16;
            uint32_t ah[4][4], al[4][4];
#pragma unroll
            for (int mt = 0; mt < 4; ++mt) {
                LDM4(ah[mt], aaddr + mt * 1280);
                LDM4(al[mt], aaddr + mt * 1280 + ARRB);
            }
            uint32_t bbase = st + 2 * ARRB + (wn * 32 + lb) * 80 + (kh * 2 + lbc) * 16;
            uint32_t bh[2][4], bl[2][4];
#pragma unroll
            for (int ntp = 0; ntp < 2; ++ntp) {
                LDM4(bh[ntp], bbase + ntp * 1280);
                LDM4(bl[ntp], bbase + ntp * 1280 + ARRB);
            }
#pragma unroll
            for (int mt = 0; mt < 4; ++mt)
#pragma unroll
                for (int ntp = 0; ntp < 2; ++ntp) {
                    MMA(acc[mt][2 * ntp + 0], ah[mt], bh[ntp][0], bh[ntp][1]);
                    MMA(acc[mt][2 * ntp + 1], ah[mt], bh[ntp][2], bh[ntp][3]);
                }
#pragma unroll
            for (int mt = 0; mt < 4; ++mt)
#pragma unroll
                for (int ntp = 0; ntp < 2; ++ntp) {
                    MMA(acc[mt][2 * ntp + 0], ah[mt], bl[ntp][0], bl[ntp][1]);
                    MMA(acc[mt][2 * ntp + 1], ah[mt], bl[ntp][2], bl[ntp][3]);
                }
#pragma unroll
            for (int mt = 0; mt < 4; ++mt)
#pragma unroll
                for (int ntp = 0; ntp < 2; ++ntp) {
                    MMA(acc[mt][2 * ntp + 0], al[mt], bh[ntp][0], bh[ntp][1]);
                    MMA(acc[mt][2 * ntp + 1], al[mt], bh[ntp][2], bh[ntp][3]);
                }
        }
        __syncthreads();
    }

#pragma unroll
    for (int mt = 0; mt < 4; ++mt) {
        int m0 = bm * 128 + wm * 64 + mt * 16 + (lane >> 2);
#pragma unroll
        for (int nt = 0; nt < 4; ++nt) {
            int n0 = bn * 128 + wn * 32 + nt * 8 + (lane & 3) * 2;
            float* a = acc[mt][nt];
            if (n0 < N) {
                float bs = bias1[n0] + (bias2 ? bias2[n0] : 0.0f);
                C[(size_t)m0 * N + n0]       = a[0] + bs;
                C[(size_t)(m0 + 8) * N + n0] = a[2] + bs;
            }
            if (n0 + 1 < N) {
                float bs = bias1[n0 + 1] + (bias2 ? bias2[n0 + 1] : 0.0f);
                C[(size_t)m0 * N + n0 + 1]       = a[1] + bs;
                C[(size_t)(m0 + 8) * N + n0 + 1] = a[3] + bs;
            }
        }
    }
}

// ---------------- persistent tensor-core LSTM recurrence ----------------
// 128 CTAs (64/dir), 384 threads = 12 warps, warp (wid&3, wid>>2) owns
// (m16, n8) tile of the [64 x 24] gate GEMM, split-bf16 3-term on mma.sync.
// h exchanged as bf16 hi/lo, double-buffered by step parity.
// B (weight) hi+lo fragments fetched with ONE ldmatrix.x4 (lanes 0-15 -> W_hi
// rows, lanes 16-31 -> W_lo rows).
#define LA_HI   0
#define LA_LO   50176           // 64 rows * 784B pitch
#define LW_HI   100352
#define LW_LO   119168          // 24 rows * 784B
#define LGATES  137984          // 64 * 26 floats
#define LCS     144640          // 384 floats
#define LSMEM   146176
#define PITCH   784

__global__ void __launch_bounds__(RTH, 1)
lstm_kernel(const float* __restrict__ Whh_f, const float* __restrict__ Whh_b)
{
    extern __shared__ char smem[];
    uint32_t sb = smem_u32(smem);
    float* gates_s = (float*)(smem + LGATES);
    float* c_s     = (float*)(smem + LCS);

    int cta = blockIdx.x;
    int dir = (cta >= NCD) ? 1 : 0;
    int ci  = cta - dir * NCD;
    const float* Whh = dir ? Whh_b : Whh_f;
    const float* xp  = dir ? g_xpb : g_xpf;
    int n0  = ci * CH;
    int tid = threadIdx.x;
    int lane = tid & 31, wid = tid >> 5;
    int mt = wid & 3;          // m-tile (16 b rows)
    int nt = wid >> 2;         // n-tile (8 gate rows)

    // ---- load + split Whh slice into SMEM (once) ----
    for (int idx = tid; idx < RR * HH; idx += RTH) {
        int r = idx / HH, k = idx - r * HH;
        int gi = r / CH, j = r - gi * CH;
        float v = Whh[(size_t)(gi * HH + n0 + j) * HH + k];
        __nv_bfloat16 h = __float2bfloat16(v);
        *(__nv_bfloat16*)(smem + LW_HI + r * PITCH + k * 2) = h;
        *(__nv_bfloat16*)(smem + LW_LO + r * PITCH + k * 2) =
            __float2bfloat16(v - __bfloat162float(h));
    }
    for (int idx = tid; idx < CH * BB; idx += RTH) c_s[idx] = 0.0f;
    __syncthreads();

    // cell-update mapping: this thread owns cell (j, b)
    int cj = tid >> 6;         // 0..5
    int cb = tid & 63;

    // ldmatrix address components
    int la  = lane & 15, lc4 = lane >> 4;
    uint32_t aAddrBase = sb + LA_HI + (mt * 16 + la) * PITCH + lc4 * 16;
    // combined B hi/lo: lanes 0-15 -> W_hi, lanes 16-31 -> W_lo (same rows)
    uint32_t bAddrBase = sb + LW_HI + ((lane >= 16) ? (LW_LO - LW_HI) : 0u)
                       + (nt * 8 + (lane & 7)) * PITCH + ((lane >> 3) & 1) * 16;

    // initial xp prefetch for step 0
    float xg[4];
    {
        int t0 = dir ? (SS - 1) : 0;
        const float* xr = &xp[((size_t)cb * SS + t0) * FOURH + n0 + cj];
#pragma unroll
        for (int gi = 0; gi < 4; ++gi) xg[gi] = __ldg(xr + gi * HH);
    }

    for (int s = 0; s < SS; ++s) {
        int t = dir ? (SS - 1 - s) : s;
        int p = s & 1;

        // ---- issue h copy: 4 chunks x (hi+lo), 4 cp16/thread/chunk ----
        const char* srcH = (const char*)&g_hbhi[dir][p][0];
        const char* srcL = (const char*)&g_hblo[dir][p][0];
#pragma unroll
        for (int q = 0; q < 4; ++q) {
#pragma unroll
            for (int i = 0; i < 2; ++i) {
                int e = i * RTH + tid;            // 0..767
                int row = e / 12, cc = e - row * 12;
                uint32_t so = row * 768 + q * 192 + cc * 16;
                uint32_t doff = row * PITCH + q * 192 + cc * 16;
                cp16(sb + LA_HI + doff, srcH + so, true);
                cp16(sb + LA_LO + doff, srcL + so, true);
            }
            CP_COMMIT();
        }

        // ---- gate GEMM: 24 k16 steps in 4 chunks ----
        float acc[4] = {0.f, 0.f, 0.f, 0.f};
#pragma unroll
        for (int q = 0; q < 4; ++q) {
            if      (q == 0) CP_WAIT(3);
            else if (q == 1) CP_WAIT(2);
            else if (q == 2) CP_WAIT(1);
            else             CP_WAIT(0);
            __syncthreads();
#pragma unroll
            for (int kk = 0; kk < 6; ++kk) {
                int k16 = q * 6 + kk;
                uint32_t ka = aAddrBase + k16 * 32;
                uint32_t kb = bAddrBase + k16 * 32;
                uint32_t ah[4], al[4], bb[4];
                LDM4(ah, ka);
                LDM4(al, ka + (LA_LO - LA_HI));
                LDM4(bb, kb);                      // bb = {bh0, bh1, bl0, bl1}
                MMA(acc, ah, bb[0], bb[1]);
                MMA(acc, ah, bb[2], bb[3]);
                MMA(acc, al, bb[0], bb[1]);
            }
        }

        // ---- epilogue: store gates to SMEM [b][r], pitch 26 ----
        {
            int brow = mt * 16 + (lane >> 2);
            int rcol = nt * 8 + (lane & 3) * 2;
            *(float2*)&gates_s[brow * 26 + rcol]       = make_float2(acc[0], acc[1]);
            *(float2*)&gates_s[(brow + 8) * 26 + rcol] = make_float2(acc[2], acc[3]);
        }
        __syncthreads();

        // ---- cell update (1 cell per thread) ----
        {
            float ig = gates_s[cb * 26 + 0 * CH + cj] + xg[0];
            float fg = gates_s[cb * 26 + 1 * CH + cj] + xg[1];
            float gg = gates_s[cb * 26 + 2 * CH + cj] + xg[2];
            float og = gates_s[cb * 26 + 3 * CH + cj] + xg[3];
            float c  = c_s[tid];
            c = sigf(fg) * c + sigf(ig) * tanhfast(gg);
            float h = sigf(og) * tanhfast(c);
            c_s[tid] = c;
            __nv_bfloat16 hh = __float2bfloat16(h);
            __nv_bfloat16 hl = __float2bfloat16(h - __bfloat162float(hh));
            int np = (s + 1) & 1;
            g_hbhi[dir][np][cb * HH + n0 + cj] = hh;
            g_hblo[dir][np][cb * HH + n0 + cj] = hl;
            size_t fo = ((size_t)cb * SS + t) * K2H + dir * HH + n0 + cj;
            g_f1hi[fo] = hh;
            g_f1lo[fo] = hl;
        }

        // ---- prefetch xp for next step (hidden under barrier) ----
        if (s + 1 < SS) {
            int t1 = dir ? (SS - 2 - s) : (s + 1);
            const float* xr = &xp[((size_t)cb * SS + t1) * FOURH + n0 + cj];
#pragma unroll
            for (int gi = 0; gi < 4; ++gi) xg[gi] = __ldg(xr + gi * HH);
        }

        // ---- inter-CTA barrier (split counters) ----
        __threadfence();
        __syncthreads();
        if (tid == 0) {
            atomicAdd(&g_bar[dir][s][ci & 7], 1u);
            const volatile unsigned* bw = &g_bar[dir][s][0];
            unsigned sum;
            do {
                sum = bw[0] + bw[1] + bw[2] + bw[3] + bw[4] + bw[5] + bw[6] + bw[7];
            } while (sum < (unsigned)NCD);
        }
        __syncthreads();
    }
}

// ---------------- launcher ----------------
extern "C" void kernel_launch(void* const* d_in, const int* in_sizes, int n_in,
                              void* d_out, int out_size)
{
    const float* f0     = (const float*)d_in[0];
    const int*   counts = (const int*)  d_in[1];
    const float* Wih_f  = (const float*)d_in[2];
    const float* Whh_f  = (const float*)d_in[3];
    const float* bih_f  = (const float*)d_in[4];
    const float* bhh_f  = (const float*)d_in[5];
    const float* Wih_b  = (const float*)d_in[6];
    const float* Whh_b  = (const float*)d_in[7];
    const float* bih_b  = (const float*)d_in[8];
    const float* bhh_b  = (const float*)d_in[9];
    const float* Wlin   = (const float*)d_in[10];
    const float* blin   = (const float*)d_in[11];
    float* out = (float*)d_out;

    void* p;
    cudaGetSymbolAddress(&p, g_xhi);     __nv_bfloat16* xhi = (__nv_bfloat16*)p;
    cudaGetSymbolAddress(&p, g_xlo);     __nv_bfloat16* xlo = (__nv_bfloat16*)p;
    cudaGetSymbolAddress(&p, g_xpf);     float* gxpf = (float*)p;
    cudaGetSymbolAddress(&p, g_xpb);     float* gxpb = (float*)p;
    cudaGetSymbolAddress(&p, g_f1hi);    __nv_bfloat16* f1hi = (__nv_bfloat16*)p;
    cudaGetSymbolAddress(&p, g_f1lo);    __nv_bfloat16* f1lo = (__nv_bfloat16*)p;
    cudaGetSymbolAddress(&p, g_wihf_hi); __nv_bfloat16* wfh = (__nv_bfloat16*)p;
    cudaGetSymbolAddress(&p, g_wihf_lo); __nv_bfloat16* wfl = (__nv_bfloat16*)p;
    cudaGetSymbolAddress(&p, g_wihb_hi); __nv_bfloat16* wbh = (__nv_bfloat16*)p;
    cudaGetSymbolAddress(&p, g_wihb_lo); __nv_bfloat16* wbl = (__nv_bfloat16*)p;
    cudaGetSymbolAddress(&p, g_wlin_hi); __nv_bfloat16* wlh = (__nv_bfloat16*)p;
    cudaGetSymbolAddress(&p, g_wlin_lo); __nv_bfloat16* wll = (__nv_bfloat16*)p;

    cudaFuncSetAttribute(lstm_kernel, cudaFuncAttributeMaxDynamicSharedMemorySize, LSMEM);
    cudaFuncSetAttribute(gemm3_kernel, cudaFuncAttributeMaxDynamicSharedMemorySize, 2 * STGB);

    init_kernel<<<4, 256>>>();
    pool_kernel<<<BB, 256>>>(f0, counts, xhi, xlo);

    int nw = FOURH * DD;
    int nl = CC * K2H;
    int ncvt = 2 * nw + nl;
    cvt3_kernel<<<(ncvt + 255) / 256, 256>>>(Wih_f, wfh, wfl, nw,
                                             Wih_b, wbh, wbl, nw,
                                             Wlin,  wlh, wll, nl);

    dim3 gproj(FOURH / 128, MM / 128);   // 12 x 256
    gemm3_kernel<<<gproj, 256, 2 * STGB>>>(xhi, xlo, wfh, wfl, bih_f, bhh_f, gxpf, FOURH, DD);
    gemm3_kernel<<<gproj, 256, 2 * STGB>>>(xhi, xlo, wbh, wbl, bih_b, bhh_b, gxpb, FOURH, DD);

    lstm_kernel<<<2 * NCD, RTH, LSMEM>>>(Whh_f, Whh_b);   // launch #5 -> ncu -s 5

    dim3 gout((CC + 127) / 128, MM / 128);  // 4 x 256
    gemm3_kernel<<<gout, 256, 2 * STGB>>>(f1hi, f1lo, wlh, wll, blin, nullptr, out, CC, K2H);
}